// round 17
// baseline (speedup 1.0000x reference)
#include <cuda_runtime.h>
#include <cuda_bf16.h>

#define HW   56
#define TS   68          // row stride: 4-aligned for vec ops, conflict-free conv
#define KSEL 30
#define NT   224         // threads: 28 row-pairs x 8 col-groups
#define NV   7           // columns per thread patch (2 rows x 7 cols = 14 px)
#define TMAX 448         // candidate capacity

__global__ __launch_bounds__(NT, 8)
void topk_spatial_kernel(const float* __restrict__ x,
                         const float* __restrict__ wgt,
                         const float* __restrict__ bias,
                         float* __restrict__ out,
                         int C)
{
    __shared__ float    tile[58 * TS];   // pixel (r,c) at [(r+1)*TS + c+4]
    __shared__ double   csc[TMAX];       // candidate exact scores
    __shared__ int      cidx[TMAX];      // candidate flat indices
    __shared__ float    wsm[10];
    __shared__ float    xmax_sm[7];
    __shared__ float    wk[7];           // per-warp rank-6 maxima
    __shared__ int      tcnt, pcnt;
    __shared__ int      plist[NT];       // tids whose max clears the band

    const int tid = threadIdx.x;
    const int bc  = blockIdx.x;
    const int ch  = bc % C;
    const float* gx = x   + (size_t)bc * (HW * HW);
    float*       go = out + (size_t)bc * (HW * HW);

    if (tid < 9)  wsm[tid] = wgt[ch * 9 + tid];
    if (tid == 9) wsm[9]   = bias[ch];
    if (tid == 10) tcnt = 0;
    if (tid == 11) pcnt = 0;

    // ---- zero borders: rows 0 & 57 (full), cols 3 & 60 (rows 1..56) ----
    for (int i = tid; i < 248; i += NT) {
        if      (i < 68)  tile[i] = 0.f;
        else if (i < 136) tile[57 * TS + (i - 68)] = 0.f;
        else if (i < 192) tile[(i - 135) * TS + 3] = 0.f;
        else              tile[(i - 191) * TS + 60] = 0.f;
    }

    // ---- load interior + ZERO-FILL out, division-free strided walk ----
    const int r0 = tid / 14;
    const int q4 = tid - r0 * 14;        // float4 index in row, col = 4*q4
    float maxv = 0.0f;
    {
        const float4 z4 = make_float4(0.f, 0.f, 0.f, 0.f);
        const float4* gp = reinterpret_cast<const float4*>(gx) + (r0 * 14 + q4);
        float4*       op = reinterpret_cast<float4*>(go)       + (r0 * 14 + q4);
        float*        tp = &tile[(r0 + 1) * TS + q4 * 4 + 4];
        #pragma unroll
        for (int it = 0; it < 4; ++it) {
            if (it < 3 || r0 < 8) {
                float4 v = *gp;
                maxv = fmaxf(maxv, fmaxf(fmaxf(fabsf(v.x), fabsf(v.y)),
                                         fmaxf(fabsf(v.z), fabsf(v.w))));
                *reinterpret_cast<float4*>(tp) = v;
                *op = z4;
            }
            gp += 16 * 14;
            op += 16 * 14;
            tp += 16 * TS;
        }
    }
    #pragma unroll
    for (int d = 16; d > 0; d >>= 1)
        maxv = fmaxf(maxv, __shfl_xor_sync(0xFFFFFFFFu, maxv, d));
    if ((tid & 31) == 0) xmax_sm[tid >> 5] = maxv;
    __syncthreads();

    const float w0 = wsm[0], w1 = wsm[1], w2 = wsm[2];
    const float w3 = wsm[3], w4 = wsm[4], w5 = wsm[5];
    const float w6 = wsm[6], w7 = wsm[7], w8 = wsm[8];
    const float bv = wsm[9];

    const int row0 = (tid >> 3) * 2;      // 0,2,...,54
    const int c0   = (tid & 7) * NV;      // 0,7,...,49
    const int lane = tid & 31;

    // ---- conv pass 1: 2x7 patch, rolling window; track ONLY the max ----
    float smax = -3.4e38f;
    {
        const float* R0 = &tile[row0 * TS + c0 + 3];
        const float* R1 = R0 + TS;
        const float* R2 = R1 + TS;
        const float* R3 = R2 + TS;
        float a00 = R0[0], a01 = R0[1];
        float a10 = R1[0], a11 = R1[1];
        float a20 = R2[0], a21 = R2[1];
        float a30 = R3[0], a31 = R3[1];
        #pragma unroll
        for (int j = 0; j < NV; ++j) {
            float a02 = R0[j + 2], a12 = R1[j + 2];
            float a22 = R2[j + 2], a32 = R3[j + 2];
            float s0 = bv;
            s0 = fmaf(w0, a00, s0); s0 = fmaf(w1, a01, s0); s0 = fmaf(w2, a02, s0);
            s0 = fmaf(w3, a10, s0); s0 = fmaf(w4, a11, s0); s0 = fmaf(w5, a12, s0);
            s0 = fmaf(w6, a20, s0); s0 = fmaf(w7, a21, s0); s0 = fmaf(w8, a22, s0);
            float s1 = bv;
            s1 = fmaf(w0, a10, s1); s1 = fmaf(w1, a11, s1); s1 = fmaf(w2, a12, s1);
            s1 = fmaf(w3, a20, s1); s1 = fmaf(w4, a21, s1); s1 = fmaf(w5, a22, s1);
            s1 = fmaf(w6, a30, s1); s1 = fmaf(w7, a31, s1); s1 = fmaf(w8, a32, s1);
            smax = fmaxf(smax, fmaxf(s0, s1));
            a00 = a01; a01 = a02; a10 = a11; a11 = a12;
            a20 = a21; a21 = a22; a30 = a31; a31 = a32;
        }
    }

    // ---- shuffle-only threshold: per-warp rank-6 of the 32 thread-maxima.
    //      Tie-removal only LOWERS kth => >=6 lanes have smax >= kth (safe). ----
    {
        float rem = smax;
        float kth = smax;
        #pragma unroll
        for (int it = 0; it < 6; ++it) {
            float m = rem;
            #pragma unroll
            for (int d = 16; d > 0; d >>= 1)
                m = fmaxf(m, __shfl_xor_sync(0xFFFFFFFFu, m, d));
            kth = m;
            if (rem == m) rem = -3.4e38f;
        }
        if (lane == 0) wk[tid >> 5] = kth;
    }
    __syncthreads();

    // ---- T = largest wk[j] with >=4 strictly greater values among the 7.
    //      => >=5 warps have kth >= T => >=30 thread-maxima >= T => V30 >= T. ----
    float k0 = wk[0], k1 = wk[1], k2 = wk[2], k3 = wk[3];
    float k4 = wk[4], k5 = wk[5], k6 = wk[6];
    float T = -3.4e38f;
    {
        float v[7] = {k0, k1, k2, k3, k4, k5, k6};
        #pragma unroll
        for (int j = 0; j < 7; ++j) {
            int cgt = 0;
            #pragma unroll
            for (int i = 0; i < 7; ++i) cgt += (v[i] > v[j]);
            if (cgt >= 4) T = fmaxf(T, v[j]);
        }
    }

    // ---- guard band: Tc = T - 2E (E = rigorous fp32 conv error bound) ----
    float xmax = xmax_sm[0];
    #pragma unroll
    for (int i = 1; i < 7; ++i) xmax = fmaxf(xmax, xmax_sm[i]);
    const float wsum = fabsf(w0) + fabsf(w1) + fabsf(w2) + fabsf(w3) + fabsf(w4)
                     + fabsf(w5) + fabsf(w6) + fabsf(w7) + fabsf(w8);
    const float E = (wsum * xmax + fabsf(bv)) * 1.2e-6f;
    const float Tc = T - 2.0f * E;

    // ---- Phase A0: passing threads publish tid (one atomic each) ----
    if (smax >= Tc) {
        int qq = atomicAdd(&pcnt, 1);
        plist[qq] = tid;                   // qq < 224 always
    }
    __syncthreads();
    const int np = pcnt;

    // ---- Phase A1 (+fused B): cooperative rescore of flagged pixels; on a hit,
    //      the 9 taps are in registers -> compute the EXACT double score now. ----
    for (int idx = tid; idx < np * 14; idx += NT) {
        int qq    = idx / 14;
        int k     = idx - qq * 14;
        int owner = plist[qq];
        int pr    = ((owner >> 3) * 2) + (k >= NV ? 1 : 0);
        int pc    = ((owner & 7) * NV) + (k >= NV ? k - NV : k);
        const float* t0 = &tile[pr * TS + pc + 3];
        float v0 = t0[0],      v1 = t0[1],      v2 = t0[2];
        float v3 = t0[TS],     v4 = t0[TS + 1], v5 = t0[TS + 2];
        float v6 = t0[2*TS],   v7 = t0[2*TS+1], v8 = t0[2*TS+2];
        float s = bv;
        s = fmaf(w0, v0, s); s = fmaf(w1, v1, s); s = fmaf(w2, v2, s);
        s = fmaf(w3, v3, s); s = fmaf(w4, v4, s); s = fmaf(w5, v5, s);
        s = fmaf(w6, v6, s); s = fmaf(w7, v7, s); s = fmaf(w8, v8, s);
        if (s >= Tc) {
            double d = (double)bv;
            d = fma((double)w0, (double)v0, d);
            d = fma((double)w1, (double)v1, d);
            d = fma((double)w2, (double)v2, d);
            d = fma((double)w3, (double)v3, d);
            d = fma((double)w4, (double)v4, d);
            d = fma((double)w5, (double)v5, d);
            d = fma((double)w6, (double)v6, d);
            d = fma((double)w7, (double)v7, d);
            d = fma((double)w8, (double)v8, d);
            int pos = atomicAdd(&tcnt, 1);
            if (pos < TMAX) { csc[pos] = d; cidx[pos] = pr * HW + pc; }
        }
    }
    __syncthreads();
    const int ntie = (tcnt < TMAX) ? tcnt : TMAX;

    // ---- Phase C: rank by (double desc, index asc); winners scatter x directly
    //      into the pre-zeroed output (ordered after zero STGs by barriers) ----
    if (tid < ntie) {
        double mys = csc[tid];
        int   cpos = cidx[tid];
        unsigned rnk = 0;
        for (int qq = 0; qq < ntie; ++qq) {
            double v = csc[qq];
            rnk += (v > mys) || (v == mys && cidx[qq] < cpos);
        }
        if (rnk < KSEL) {
            int r = cpos / HW, cc = cpos - r * HW;
            go[cpos] = tile[(r + 1) * TS + cc + 4];
        }
    }
}

extern "C" void kernel_launch(void* const* d_in, const int* in_sizes, int n_in,
                              void* d_out, int out_size)
{
    const float* x  = (const float*)d_in[0];
    const float* w  = (const float*)d_in[1];
    const float* b  = (const float*)d_in[2];
    float*       o  = (float*)d_out;
    int C    = in_sizes[2];               // 384
    int n_bc = in_sizes[0] / (HW * HW);   // 12288
    topk_spatial_kernel<<<n_bc, NT>>>(x, w, b, o, C);
}